// round 6
// baseline (speedup 1.0000x reference)
#include <cuda_runtime.h>
#include <cuda_bf16.h>
#include <stdint.h>
#include <math.h>

// Problem constants: N=50000, E=800000, K=16, D=128, H=8, DH=16
#define NMAX 50000
#define EMAX 800000
#define NTILE 391                     // ceil(50000/128)
#define NPAD  (NTILE * 128)           // 50048 padded rows
#define SCALE_Q 0.08838834764831845f  // 128^-0.5

// -------- scratch (device globals; zero-initialized) --------
__device__ __nv_bfloat16 g_xln [(size_t)NPAD * 128];
__device__ __nv_bfloat16 g_attn[(size_t)NPAD * 128];
__device__ __nv_bfloat16 g_hid [(size_t)NPAD * 512];
__device__ __nv_bfloat16 g_qkv [(size_t)NPAD * 384];
__device__ float         g_scores[(size_t)EMAX * 8];
__device__ float         g_x2[(size_t)NMAX * 128];
// bf16 W^T, [N][K] K-major
__device__ __nv_bfloat16 g_wq[384 * 128];
__device__ __nv_bfloat16 g_wr[128 * 128];
__device__ __nv_bfloat16 g_w1[512 * 128];
__device__ __nv_bfloat16 g_w2[128 * 512];

// -------- helpers --------
__device__ __forceinline__ uint32_t smem_u32(const void* p)
{
    uint32_t a;
    asm("{ .reg .u64 t; cvta.to.shared.u64 t, %1; cvt.u32.u64 %0, t; }" : "=r"(a) : "l"(p));
    return a;
}
__device__ __forceinline__ void cp16(uint32_t dst, const void* src)
{
    asm volatile("cp.async.cg.shared.global [%0], [%1], 16;" :: "r"(dst), "l"(src));
}
__device__ __forceinline__ void ldsm_x4(uint32_t* r, uint32_t addr)
{
    asm volatile("ldmatrix.sync.aligned.m8n8.x4.shared.b16 {%0,%1,%2,%3}, [%4];"
                 : "=r"(r[0]), "=r"(r[1]), "=r"(r[2]), "=r"(r[3]) : "r"(addr));
}
__device__ __forceinline__ void mma16816(float* acc, const uint32_t* a,
                                         uint32_t b0, uint32_t b1)
{
    asm volatile(
        "mma.sync.aligned.m16n8k16.row.col.f32.bf16.bf16.f32 "
        "{%0,%1,%2,%3}, {%4,%5,%6,%7}, {%8,%9}, {%0,%1,%2,%3};"
        : "+f"(acc[0]), "+f"(acc[1]), "+f"(acc[2]), "+f"(acc[3])
        : "r"(a[0]), "r"(a[1]), "r"(a[2]), "r"(a[3]), "r"(b0), "r"(b1));
}
__device__ __forceinline__ int swzo(int c2, int sw)
{
    return (c2 & ~127) | ((c2 & 127) ^ sw);
}
__device__ __forceinline__ float gelu_f(float x)
{
    float x3 = x * x * x;
    return 0.5f * x * (1.0f + tanhf(0.7978845608028654f * (x + 0.044715f * x3)));
}

// ---------------------------------------------------------------------------
// Weight prep: f32 W[K,N] -> bf16 W^T[n][k]
// ---------------------------------------------------------------------------
__global__ void prep_weights(const float* __restrict__ wq, const float* __restrict__ wr,
                             const float* __restrict__ w1, const float* __restrict__ w2,
                             __nv_bfloat16* bq, __nv_bfloat16* br,
                             __nv_bfloat16* b1, __nv_bfloat16* b2)
{
    int i = blockIdx.x * 256 + threadIdx.x;          // 0..196607
    if (i < 49152) {                                 // qkv_w: K=128, N=384
        int n = i >> 7, k = i & 127;
        bq[i] = __float2bfloat16_rn(wq[k * 384 + n]);
    } else if (i < 49152 + 16384) {                  // res_in_w 128x128
        int j = i - 49152;
        int n = j >> 7, k = j & 127;
        br[j] = __float2bfloat16_rn(wr[k * 128 + n]);
    } else if (i < 49152 + 16384 + 65536) {          // ffn_in_w: K=128, N=512
        int j = i - 49152 - 16384;
        int n = j >> 7, k = j & 127;
        b1[j] = __float2bfloat16_rn(w1[k * 512 + n]);
    } else {                                         // ffn_out_w: K=512, N=128
        int j = i - 49152 - 16384 - 65536;
        int n = j >> 9, k = j & 511;
        b2[j] = __float2bfloat16_rn(w2[k * 128 + n]);
    }
}

// ---------------------------------------------------------------------------
// LayerNorm: one row per warp; fp32 in, bf16 out
// ---------------------------------------------------------------------------
__global__ void ln_kernel(const float* __restrict__ x, const float* __restrict__ g,
                          const float* __restrict__ b, __nv_bfloat16* __restrict__ y, int n)
{
    int row = blockIdx.x * blockDim.y + threadIdx.y;
    if (row >= n) return;
    int lane = threadIdx.x;
    float4 v = reinterpret_cast<const float4*>(x + (size_t)row * 128)[lane];
    float s = v.x + v.y + v.z + v.w;
#pragma unroll
    for (int o = 16; o > 0; o >>= 1) s += __shfl_xor_sync(0xffffffffu, s, o);
    float mean = s * 0.0078125f;
    float dx = v.x - mean, dy = v.y - mean, dz = v.z - mean, dw = v.w - mean;
    float ss = dx * dx + dy * dy + dz * dz + dw * dw;
#pragma unroll
    for (int o = 16; o > 0; o >>= 1) ss += __shfl_xor_sync(0xffffffffu, ss, o);
    float inv = rsqrtf(ss * 0.0078125f + 1e-5f);
    float4 gg = reinterpret_cast<const float4*>(g)[lane];
    float4 bb = reinterpret_cast<const float4*>(b)[lane];
    __nv_bfloat162 o0 = __floats2bfloat162_rn(dx * inv * gg.x + bb.x, dy * inv * gg.y + bb.y);
    __nv_bfloat162 o1 = __floats2bfloat162_rn(dz * inv * gg.z + bb.z, dw * inv * gg.w + bb.w);
    uint2 pack;
    pack.x = *reinterpret_cast<uint32_t*>(&o0);
    pack.y = *reinterpret_cast<uint32_t*>(&o1);
    reinterpret_cast<uint2*>(y + (size_t)row * 128)[lane] = pack;
}

// ---------------------------------------------------------------------------
// bf16 mma.sync GEMM (ldmatrix + cp.async 2-stage pipeline)
// BM=128, BN=128, 256 threads (8 warps: 4m x 2n), warp tile 32x64.
// EPI: 0 qkv->bf16 (scale gy==0), 2 gelu->bf16, 3 +res->f32,
//      4 +res->f32 x2 AND fused LayerNorm -> Y2 bf16
// ---------------------------------------------------------------------------
template <int EPI, int KTOT, int CK>
__global__ void __launch_bounds__(256) gemm_mma(
    const __nv_bfloat16* __restrict__ A, const __nv_bfloat16* __restrict__ WT,
    const float* __restrict__ bias, const float* __restrict__ res,
    void* __restrict__ Cv, int M,
    const float* __restrict__ lng, const float* __restrict__ lnb,
    __nv_bfloat16* __restrict__ Y2)
{
    constexpr int CHUNKS = KTOT / CK;
    constexpr int STAGES = (CHUNKS > 1) ? 2 : 1;
    constexpr int ROWB   = CK * 2;
    constexpr int HALF   = 128 * ROWB;
    constexpr int STAGE  = 2 * HALF;
    constexpr int CPR    = CK / 8;

    extern __shared__ char smraw[];
    const uint32_t sbase = smem_u32(smraw);

    const int tid  = threadIdx.x;
    const int lane = tid & 31;
    const int warp = tid >> 5;
    const int mw = warp & 3;
    const int nw = warp >> 2;

    const char* Ab  = (const char*)(A  + (size_t)blockIdx.x * 128 * KTOT);
    const char* WTb = (const char*)(WT + (size_t)blockIdx.y * 128 * KTOT);

    float acc[2][8][4];
#pragma unroll
    for (int mt = 0; mt < 2; mt++)
#pragma unroll
        for (int nt = 0; nt < 8; nt++)
#pragma unroll
            for (int c = 0; c < 4; c++) acc[mt][nt][c] = 0.0f;

    int aoff[2], asw[2];
#pragma unroll
    for (int mt = 0; mt < 2; mt++) {
        int r = mw * 32 + mt * 16 + (lane & 7) + ((lane >> 3) & 1) * 8;
        aoff[mt] = r * ROWB;
        asw[mt]  = (r & 7) << 4;
    }
    const int akh = ((lane >> 4) & 1) * 16;
    int boff[4], bsw[4];
#pragma unroll
    for (int p = 0; p < 4; p++) {
        int r = nw * 64 + p * 16 + ((lane >> 4) & 1) * 8 + (lane & 7);
        boff[p] = r * ROWB;
        bsw[p]  = (r & 7) << 4;
    }
    const int bkh = ((lane >> 3) & 1) * 16;

    auto load_chunk = [&](int s, int c) {
        uint32_t dA = sbase + s * STAGE;
        uint32_t dB = dA + HALF;
#pragma unroll
        for (int i = tid; i < 16 * CK; i += 256) {
            int row = i / CPR, cc = i % CPR;
            int so = swzo(cc * 16, (row & 7) << 4);
            cp16(dA + row * ROWB + so,
                 Ab + (size_t)row * (KTOT * 2) + c * (CK * 2) + cc * 16);
            cp16(dB + row * ROWB + so,
                 WTb + (size_t)row * (KTOT * 2) + c * (CK * 2) + cc * 16);
        }
        asm volatile("cp.async.commit_group;" ::: "memory");
    };

    auto compute = [&](int s) {
        uint32_t bA = sbase + s * STAGE;
        uint32_t bB = bA + HALF;
#pragma unroll
        for (int kk = 0; kk < CK; kk += 16) {
            uint32_t a[2][4], bb[4][4];
#pragma unroll
            for (int mt = 0; mt < 2; mt++)
                ldsm_x4(a[mt], bA + aoff[mt] + swzo(kk * 2 + akh, asw[mt]));
#pragma unroll
            for (int p = 0; p < 4; p++)
                ldsm_x4(bb[p], bB + boff[p] + swzo(kk * 2 + bkh, bsw[p]));
#pragma unroll
            for (int mt = 0; mt < 2; mt++)
#pragma unroll
                for (int nt = 0; nt < 8; nt++) {
                    int p = nt >> 1, hi = (nt & 1) * 2;
                    mma16816(acc[mt][nt], a[mt], bb[p][hi], bb[p][hi + 1]);
                }
        }
    };

    load_chunk(0, 0);
    if (CHUNKS > 1) load_chunk(1, 1);

#pragma unroll 1
    for (int c = 0; c < CHUNKS; c++) {
        if (CHUNKS > 1 && c < CHUNKS - 1)
            asm volatile("cp.async.wait_group 1;" ::: "memory");
        else
            asm volatile("cp.async.wait_group 0;" ::: "memory");
        __syncthreads();
        compute(c & (STAGES - 1));
        if (CHUNKS > 1 && c + 2 <= CHUNKS - 1) {
            __syncthreads();
            load_chunk(c & 1, c + 2);
        }
    }

    // ---- epilogue ----
    const int g4 = lane >> 2, t4 = lane & 3;
    if (EPI == 4) {
        // x2 = acc + bias + res (f32 out), then fused LayerNorm -> Y2 (bf16)
        float psum[2][2], psq[2][2];
#pragma unroll
        for (int mt = 0; mt < 2; mt++) { psum[mt][0] = psum[mt][1] = 0.f; psq[mt][0] = psq[mt][1] = 0.f; }
        float* out = (float*)Cv;
#pragma unroll
        for (int mt = 0; mt < 2; mt++) {
            int rA = blockIdx.x * 128 + mw * 32 + mt * 16 + g4;
#pragma unroll
            for (int nt = 0; nt < 8; nt++) {
                int cl = nw * 64 + nt * 8 + 2 * t4;
                float b0 = bias[cl], b1 = bias[cl + 1];
                float v0 = 0.f, v1 = 0.f, v2 = 0.f, v3 = 0.f;
                if (rA < M) {
                    float2 rr = *reinterpret_cast<const float2*>(res + (size_t)rA * 128 + cl);
                    v0 = acc[mt][nt][0] + b0 + rr.x;
                    v1 = acc[mt][nt][1] + b1 + rr.y;
                    *reinterpret_cast<float2*>(out + (size_t)rA * 128 + cl) = make_float2(v0, v1);
                }
                if (rA + 8 < M) {
                    float2 rr = *reinterpret_cast<const float2*>(res + (size_t)(rA + 8) * 128 + cl);
                    v2 = acc[mt][nt][2] + b0 + rr.x;
                    v3 = acc[mt][nt][3] + b1 + rr.y;
                    *reinterpret_cast<float2*>(out + (size_t)(rA + 8) * 128 + cl) = make_float2(v2, v3);
                }
                acc[mt][nt][0] = v0; acc[mt][nt][1] = v1;
                acc[mt][nt][2] = v2; acc[mt][nt][3] = v3;
                psum[mt][0] += v0 + v1;       psq[mt][0] += v0 * v0 + v1 * v1;
                psum[mt][1] += v2 + v3;       psq[mt][1] += v2 * v2 + v3 * v3;
            }
        }
        // quad reduce over t4 (lane bits 0..1)
#pragma unroll
        for (int mt = 0; mt < 2; mt++)
#pragma unroll
            for (int hf = 0; hf < 2; hf++)
#pragma unroll
                for (int o = 1; o < 4; o <<= 1) {
                    psum[mt][hf] += __shfl_xor_sync(0xffffffffu, psum[mt][hf], o);
                    psq[mt][hf]  += __shfl_xor_sync(0xffffffffu, psq[mt][hf], o);
                }
        __syncthreads();                       // tiles no longer needed; reuse smem
        float* ss = (float*)smraw;             // [rl][nw][2]
        if (t4 == 0) {
#pragma unroll
            for (int mt = 0; mt < 2; mt++)
#pragma unroll
                for (int hf = 0; hf < 2; hf++) {
                    int rl = mw * 32 + mt * 16 + g4 + hf * 8;
                    ss[rl * 4 + nw * 2 + 0] = psum[mt][hf];
                    ss[rl * 4 + nw * 2 + 1] = psq[mt][hf];
                }
        }
        __syncthreads();
        float gv[8][2], bv[8][2];
#pragma unroll
        for (int nt = 0; nt < 8; nt++) {
            int cl = nw * 64 + nt * 8 + 2 * t4;
            float2 gg = *reinterpret_cast<const float2*>(lng + cl);
            float2 bb = *reinterpret_cast<const float2*>(lnb + cl);
            gv[nt][0] = gg.x; gv[nt][1] = gg.y;
            bv[nt][0] = bb.x; bv[nt][1] = bb.y;
        }
#pragma unroll
        for (int mt = 0; mt < 2; mt++)
#pragma unroll
            for (int hf = 0; hf < 2; hf++) {
                int rl = mw * 32 + mt * 16 + g4 + hf * 8;
                float s = ss[rl * 4 + 0] + ss[rl * 4 + 2];
                float q = ss[rl * 4 + 1] + ss[rl * 4 + 3];
                float mean = s * 0.0078125f;
                float var  = q * 0.0078125f - mean * mean;
                float inv  = rsqrtf(var + 1e-5f);
                size_t rowo = (size_t)(blockIdx.x * 128 + rl) * 128;
#pragma unroll
                for (int nt = 0; nt < 8; nt++) {
                    int cl = nw * 64 + nt * 8 + 2 * t4;
                    float x0 = acc[mt][nt][hf * 2 + 0];
                    float x1 = acc[mt][nt][hf * 2 + 1];
                    float y0 = (x0 - mean) * inv * gv[nt][0] + bv[nt][0];
                    float y1 = (x1 - mean) * inv * gv[nt][1] + bv[nt][1];
                    *reinterpret_cast<__nv_bfloat162*>(Y2 + rowo + cl) =
                        __floats2bfloat162_rn(y0, y1);
                }
            }
        return;
    }

#pragma unroll
    for (int mt = 0; mt < 2; mt++) {
        int row = blockIdx.x * 128 + mw * 32 + mt * 16 + g4;
#pragma unroll
        for (int nt = 0; nt < 8; nt++) {
            int cl = nw * 64 + nt * 8 + 2 * t4;
            float* ac = acc[mt][nt];
            if (EPI == 0) {
                int cg = blockIdx.y * 128 + cl;
                float b0 = bias[cg], b1 = bias[cg + 1];
                float v0 = ac[0] + b0, v1 = ac[1] + b1;
                float v2 = ac[2] + b0, v3 = ac[3] + b1;
                if (blockIdx.y == 0) { v0 *= SCALE_Q; v1 *= SCALE_Q; v2 *= SCALE_Q; v3 *= SCALE_Q; }
                __nv_bfloat16* out = (__nv_bfloat16*)Cv;
                *reinterpret_cast<__nv_bfloat162*>(out + (size_t)row * 384 + cg) =
                    __floats2bfloat162_rn(v0, v1);
                *reinterpret_cast<__nv_bfloat162*>(out + (size_t)(row + 8) * 384 + cg) =
                    __floats2bfloat162_rn(v2, v3);
            } else if (EPI == 2) {
                int cg = blockIdx.y * 128 + cl;
                float b0 = bias[cg], b1 = bias[cg + 1];
                __nv_bfloat16* out = (__nv_bfloat16*)Cv;
                *reinterpret_cast<__nv_bfloat162*>(out + (size_t)row * 512 + cg) =
                    __floats2bfloat162_rn(gelu_f(ac[0] + b0), gelu_f(ac[1] + b1));
                *reinterpret_cast<__nv_bfloat162*>(out + (size_t)(row + 8) * 512 + cg) =
                    __floats2bfloat162_rn(gelu_f(ac[2] + b0), gelu_f(ac[3] + b1));
            } else {  // EPI 3: f32 out + residual, N=128
                float b0 = bias[cl], b1 = bias[cl + 1];
                float* out = (float*)Cv;
                if (row < M) {
                    float2 rr = *reinterpret_cast<const float2*>(res + (size_t)row * 128 + cl);
                    *reinterpret_cast<float2*>(out + (size_t)row * 128 + cl) =
                        make_float2(ac[0] + b0 + rr.x, ac[1] + b1 + rr.y);
                }
                if (row + 8 < M) {
                    float2 rr = *reinterpret_cast<const float2*>(res + (size_t)(row + 8) * 128 + cl);
                    *reinterpret_cast<float2*>(out + (size_t)(row + 8) * 128 + cl) =
                        make_float2(ac[2] + b0 + rr.x, ac[3] + b1 + rr.y);
                }
            }
        }
    }
}

// ---------------------------------------------------------------------------
// Edge scores: one head per lane (8 lanes per edge) — L2-BW-bound floor
// ---------------------------------------------------------------------------
__global__ void edge_scores_kernel(const int* __restrict__ src, const int* __restrict__ dst,
                                   const float* __restrict__ eb,
                                   const __nv_bfloat16* __restrict__ qkv,
                                   float* __restrict__ scores, int E)
{
    int gt = blockIdx.x * blockDim.x + threadIdx.x;
    int e = gt >> 3;
    if (e >= E) return;
    int h = gt & 7;
    int s = src[e], d = dst[e];
    const uint4* qp = reinterpret_cast<const uint4*>(qkv + (size_t)s * 384 + h * 16);
    const uint4* kp = reinterpret_cast<const uint4*>(qkv + (size_t)d * 384 + 128 + h * 16);
    uint4 q0 = qp[0], q1 = qp[1];
    uint4 k0 = kp[0], k1 = kp[1];
    float acc = 0.0f;
#define DOT2(ua, ub) { \
    float2 fa = __bfloat1622float2(*reinterpret_cast<__nv_bfloat162*>(&(ua))); \
    float2 fb = __bfloat1622float2(*reinterpret_cast<__nv_bfloat162*>(&(ub))); \
    acc = fmaf(fa.x, fb.x, acc); acc = fmaf(fa.y, fb.y, acc); }
    DOT2(q0.x, k0.x) DOT2(q0.y, k0.y) DOT2(q0.z, k0.z) DOT2(q0.w, k0.w)
    DOT2(q1.x, k1.x) DOT2(q1.y, k1.y) DOT2(q1.z, k1.z) DOT2(q1.w, k1.w)
#undef DOT2
    scores[(size_t)e * 8 + h] = acc + eb[(size_t)e * 8 + h];
}

// ---------------------------------------------------------------------------
// Aggregation: 2 nodes per 128-thread block; softmax once per (node, head)
// ---------------------------------------------------------------------------
__global__ void aggregate_kernel(const int* __restrict__ inc_idx, const int* __restrict__ src,
                                 const float* __restrict__ scores,
                                 const __nv_bfloat16* __restrict__ qkv,
                                 __nv_bfloat16* __restrict__ attn, int N)
{
    int tid = threadIdx.x;
    int base_n = blockIdx.x * 2;
    __shared__ int   e_sm[2][16];
    __shared__ int   vrow[2][16];
    __shared__ float s_sm[2][16][8];
    __shared__ float w_sm[2][16][8];

    if (tid < 32) {
        int which = tid >> 4, k = tid & 15;
        int n = base_n + which;
        int e = 0;
        if (n < N) {
            e = inc_idx[(size_t)n * 16 + k];
            if (e < 0) e = 0;
        }
        e_sm[which][k] = e;
        vrow[which][k] = src[e];
    }
    __syncthreads();
#pragma unroll
    for (int i = tid; i < 256; i += 128) {
        int which = i >> 7, r = i & 127, k = r >> 3, h = r & 7;
        s_sm[which][k][h] = scores[(size_t)e_sm[which][k] * 8 + h];
    }
    __syncthreads();
    if (tid < 16) {
        int which = tid >> 3, h = tid & 7;
        float mx = -1e30f;
#pragma unroll
        for (int k = 0; k < 16; k++) mx = fmaxf(mx, s_sm[which][k][h]);
        float ex[16], se = 0.0f;
#pragma unroll
        for (int k = 0; k < 16; k++) { ex[k] = __expf(s_sm[which][k][h] - mx); se += ex[k]; }
        float inv = 1.0f / se;
#pragma unroll
        for (int k = 0; k < 16; k++) w_sm[which][k][h] = ex[k] * inv;
    }
    __syncthreads();

    int which = tid >> 6, lt = tid & 63, dd = lt * 2, h = dd >> 4;
    int n = base_n + which;
    if (n < N) {
        float a0 = 0.0f, a1 = 0.0f;
#pragma unroll
        for (int k = 0; k < 16; k++) {
            uint32_t u = *reinterpret_cast<const uint32_t*>(
                qkv + (size_t)vrow[which][k] * 384 + 256 + dd);
            float2 f = __bfloat1622float2(*reinterpret_cast<__nv_bfloat162*>(&u));
            float w = w_sm[which][k][h];
            a0 = fmaf(w, f.x, a0);
            a1 = fmaf(w, f.y, a1);
        }
        *reinterpret_cast<__nv_bfloat162*>(attn + (size_t)n * 128 + dd) =
            __floats2bfloat162_rn(a0, a1);
    }
}

// ---------------------------------------------------------------------------
// Host launcher
// ---------------------------------------------------------------------------
extern "C" void kernel_launch(void* const* d_in, const int* in_sizes, int n_in,
                              void* d_out, int out_size)
{
    const float* triplet   = (const float*)d_in[0];
    const int*   src       = (const int*)  d_in[2];
    const int*   dst       = (const int*)  d_in[3];
    const float* edge_bias = (const float*)d_in[4];
    const int*   inc_idx   = (const int*)  d_in[6];
    const float* ln1_g     = (const float*)d_in[8];
    const float* ln1_b     = (const float*)d_in[9];
    const float* qkv_w     = (const float*)d_in[10];
    const float* qkv_b     = (const float*)d_in[11];
    const float* res_in_w  = (const float*)d_in[12];
    const float* res_in_b  = (const float*)d_in[13];
    const float* res_ln_g  = (const float*)d_in[14];
    const float* res_ln_b  = (const float*)d_in[15];
    const float* ffn_in_w  = (const float*)d_in[16];
    const float* ffn_in_b  = (const float*)d_in[17];
    const float* ffn_out_w = (const float*)d_in[18];
    const float* ffn_out_b = (const float*)d_in[19];

    const int N = in_sizes[0] / 128;
    const int E = in_sizes[2];
    const int NT = (N + 127) / 128;

    __nv_bfloat16 *xln, *attn, *hid, *qkv, *wq, *wr, *w1, *w2;
    float *scores, *x2;
    cudaGetSymbolAddress((void**)&xln,    g_xln);
    cudaGetSymbolAddress((void**)&attn,   g_attn);
    cudaGetSymbolAddress((void**)&hid,    g_hid);
    cudaGetSymbolAddress((void**)&qkv,    g_qkv);
    cudaGetSymbolAddress((void**)&scores, g_scores);
    cudaGetSymbolAddress((void**)&x2,     g_x2);
    cudaGetSymbolAddress((void**)&wq,     g_wq);
    cudaGetSymbolAddress((void**)&wr,     g_wr);
    cudaGetSymbolAddress((void**)&w1,     g_w1);
    cudaGetSymbolAddress((void**)&w2,     g_w2);

    const int SMEM = 65536;
    cudaFuncSetAttribute(gemm_mma<0, 128, 64>, cudaFuncAttributeMaxDynamicSharedMemorySize, SMEM);
    cudaFuncSetAttribute(gemm_mma<4, 128, 64>, cudaFuncAttributeMaxDynamicSharedMemorySize, SMEM);
    cudaFuncSetAttribute(gemm_mma<2, 128, 64>, cudaFuncAttributeMaxDynamicSharedMemorySize, SMEM);
    cudaFuncSetAttribute(gemm_mma<3, 512, 64>, cudaFuncAttributeMaxDynamicSharedMemorySize, SMEM);

    dim3 lnb(32, 8);
    int  lng = (N + 7) / 8;

    // 0) weight prep
    prep_weights<<<768, 256>>>(qkv_w, res_in_w, ffn_in_w, ffn_out_w, wq, wr, w1, w2);

    // 1) xln = LN(triplet_h)
    ln_kernel<<<lng, lnb>>>(triplet, ln1_g, ln1_b, xln, N);

    // 2) qkv = xln @ qkv_w + qkv_b
    gemm_mma<0, 128, 64><<<dim3(NT, 3), 256, SMEM>>>(xln, wq, qkv_b, nullptr, qkv, N,
                                                     nullptr, nullptr, nullptr);

    // 3) edge scores
    edge_scores_kernel<<<(E * 8 + 255) / 256, 256>>>(src, dst, edge_bias, qkv, scores, E);

    // 4) aggregation
    aggregate_kernel<<<(N + 1) / 2, 128>>>(inc_idx, src, scores, qkv, attn, N);

    // 5) x2 = triplet_h + attn @ res_in_w + res_in_b, fused LN2 -> xln
    gemm_mma<4, 128, 64><<<dim3(NT, 1), 256, SMEM>>>(attn, wr, res_in_b, triplet, x2, N,
                                                     res_ln_g, res_ln_b, xln);

    // 6) hid = gelu(xln @ ffn_in_w + ffn_in_b)
    gemm_mma<2, 128, 64><<<dim3(NT, 4), 256, SMEM>>>(xln, w1, ffn_in_b, nullptr, hid, N,
                                                     nullptr, nullptr, nullptr);

    // 7) out = x2 + hid @ ffn_out_w + ffn_out_b
    gemm_mma<3, 512, 64><<<dim3(NT, 1), 256, SMEM>>>(hid, w2, ffn_out_b, x2, d_out, N,
                                                     nullptr, nullptr, nullptr);
}

// round 7
// speedup vs baseline: 1.1000x; 1.1000x over previous
#include <cuda_runtime.h>
#include <cuda_bf16.h>
#include <stdint.h>
#include <math.h>

// Problem constants: N=50000, E=800000, K=16, D=128, H=8, DH=16
#define NMAX 50000
#define EMAX 800000
#define NTILE 391
#define NPAD  (NTILE * 128)
#define SCALE_Q 0.08838834764831845f

// -------- scratch --------
__device__ __nv_bfloat16 g_xln [(size_t)NPAD * 128];
__device__ __nv_bfloat16 g_attn[(size_t)NPAD * 128];
__device__ __nv_bfloat16 g_hid [(size_t)NPAD * 512];
__device__ __nv_bfloat16 g_qkv [(size_t)NPAD * 384];
__device__ float         g_x2[(size_t)NMAX * 128];
__device__ __nv_bfloat16 g_wq[384 * 128];
__device__ __nv_bfloat16 g_wr[128 * 128];
__device__ __nv_bfloat16 g_w1[512 * 128];
__device__ __nv_bfloat16 g_w2[128 * 512];

// -------- helpers --------
__device__ __forceinline__ uint32_t smem_u32(const void* p)
{
    uint32_t a;
    asm("{ .reg .u64 t; cvta.to.shared.u64 t, %1; cvt.u32.u64 %0, t; }" : "=r"(a) : "l"(p));
    return a;
}
__device__ __forceinline__ void cp16(uint32_t dst, const void* src)
{
    asm volatile("cp.async.cg.shared.global [%0], [%1], 16;" :: "r"(dst), "l"(src));
}
__device__ __forceinline__ void ldsm_x4(uint32_t* r, uint32_t addr)
{
    asm volatile("ldmatrix.sync.aligned.m8n8.x4.shared.b16 {%0,%1,%2,%3}, [%4];"
                 : "=r"(r[0]), "=r"(r[1]), "=r"(r[2]), "=r"(r[3]) : "r"(addr));
}
__device__ __forceinline__ void mma16816(float* acc, const uint32_t* a,
                                         uint32_t b0, uint32_t b1)
{
    asm volatile(
        "mma.sync.aligned.m16n8k16.row.col.f32.bf16.bf16.f32 "
        "{%0,%1,%2,%3}, {%4,%5,%6,%7}, {%8,%9}, {%0,%1,%2,%3};"
        : "+f"(acc[0]), "+f"(acc[1]), "+f"(acc[2]), "+f"(acc[3])
        : "r"(a[0]), "r"(a[1]), "r"(a[2]), "r"(a[3]), "r"(b0), "r"(b1));
}
__device__ __forceinline__ int swzo(int c2, int sw)
{
    return (c2 & ~127) | ((c2 & 127) ^ sw);
}
__device__ __forceinline__ float gelu_f(float x)
{
    float x3 = x * x * x;
    return 0.5f * x * (1.0f + tanhf(0.7978845608028654f * (x + 0.044715f * x3)));
}

// ---------------------------------------------------------------------------
// Weight prep: f32 W[K,N] -> bf16 W^T[n][k]
// ---------------------------------------------------------------------------
__global__ void prep_weights(const float* __restrict__ wq, const float* __restrict__ wr,
                             const float* __restrict__ w1, const float* __restrict__ w2,
                             __nv_bfloat16* bq, __nv_bfloat16* br,
                             __nv_bfloat16* b1, __nv_bfloat16* b2)
{
    int i = blockIdx.x * 256 + threadIdx.x;
    if (i < 49152) {
        int n = i >> 7, k = i & 127;
        bq[i] = __float2bfloat16_rn(wq[k * 384 + n]);
    } else if (i < 49152 + 16384) {
        int j = i - 49152;
        int n = j >> 7, k = j & 127;
        br[j] = __float2bfloat16_rn(wr[k * 128 + n]);
    } else if (i < 49152 + 16384 + 65536) {
        int j = i - 49152 - 16384;
        int n = j >> 7, k = j & 127;
        b1[j] = __float2bfloat16_rn(w1[k * 512 + n]);
    } else {
        int j = i - 49152 - 16384 - 65536;
        int n = j >> 9, k = j & 511;
        b2[j] = __float2bfloat16_rn(w2[k * 128 + n]);
    }
}

// ---------------------------------------------------------------------------
// LayerNorm: one row per warp; fp32 in, bf16 out
// ---------------------------------------------------------------------------
__global__ void ln_kernel(const float* __restrict__ x, const float* __restrict__ g,
                          const float* __restrict__ b, __nv_bfloat16* __restrict__ y, int n)
{
    int row = blockIdx.x * blockDim.y + threadIdx.y;
    if (row >= n) return;
    int lane = threadIdx.x;
    float4 v = reinterpret_cast<const float4*>(x + (size_t)row * 128)[lane];
    float s = v.x + v.y + v.z + v.w;
#pragma unroll
    for (int o = 16; o > 0; o >>= 1) s += __shfl_xor_sync(0xffffffffu, s, o);
    float mean = s * 0.0078125f;
    float dx = v.x - mean, dy = v.y - mean, dz = v.z - mean, dw = v.w - mean;
    float ss = dx * dx + dy * dy + dz * dz + dw * dw;
#pragma unroll
    for (int o = 16; o > 0; o >>= 1) ss += __shfl_xor_sync(0xffffffffu, ss, o);
    float inv = rsqrtf(ss * 0.0078125f + 1e-5f);
    float4 gg = reinterpret_cast<const float4*>(g)[lane];
    float4 bb = reinterpret_cast<const float4*>(b)[lane];
    __nv_bfloat162 o0 = __floats2bfloat162_rn(dx * inv * gg.x + bb.x, dy * inv * gg.y + bb.y);
    __nv_bfloat162 o1 = __floats2bfloat162_rn(dz * inv * gg.z + bb.z, dw * inv * gg.w + bb.w);
    uint2 pack;
    pack.x = *reinterpret_cast<uint32_t*>(&o0);
    pack.y = *reinterpret_cast<uint32_t*>(&o1);
    reinterpret_cast<uint2*>(y + (size_t)row * 128)[lane] = pack;
}

// ---------------------------------------------------------------------------
// bf16 mma.sync GEMM (ldmatrix + cp.async), 2 CTAs/SM target.
// BM=128, BN=128, 256 threads (8 warps: 4m x 2n), warp tile 32x64.
// EPI: 0 qkv->bf16 (scale gy==0), 1/3 +res->f32, 2 gelu->bf16
// ---------------------------------------------------------------------------
template <int EPI, int KTOT, int CK>
__global__ void __launch_bounds__(256, 2) gemm_mma(
    const __nv_bfloat16* __restrict__ A, const __nv_bfloat16* __restrict__ WT,
    const float* __restrict__ bias, const float* __restrict__ res,
    void* __restrict__ Cv, int M)
{
    constexpr int CHUNKS = KTOT / CK;
    constexpr int STAGES = (CHUNKS > 1) ? 2 : 1;
    constexpr int ROWB   = CK * 2;
    constexpr int HALF   = 128 * ROWB;
    constexpr int STAGE  = 2 * HALF;
    constexpr int CPR    = CK / 8;

    extern __shared__ char smraw[];
    const uint32_t sbase = smem_u32(smraw);

    const int tid  = threadIdx.x;
    const int lane = tid & 31;
    const int warp = tid >> 5;
    const int mw = warp & 3;
    const int nw = warp >> 2;

    const char* Ab  = (const char*)(A  + (size_t)blockIdx.x * 128 * KTOT);
    const char* WTb = (const char*)(WT + (size_t)blockIdx.y * 128 * KTOT);

    float acc[2][8][4];
#pragma unroll
    for (int mt = 0; mt < 2; mt++)
#pragma unroll
        for (int nt = 0; nt < 8; nt++)
#pragma unroll
            for (int c = 0; c < 4; c++) acc[mt][nt][c] = 0.0f;

    int aoff[2], asw[2];
#pragma unroll
    for (int mt = 0; mt < 2; mt++) {
        int r = mw * 32 + mt * 16 + (lane & 7) + ((lane >> 3) & 1) * 8;
        aoff[mt] = r * ROWB;
        asw[mt]  = (r & 7) << 4;
    }
    const int akh = ((lane >> 4) & 1) * 16;
    int boff[4], bsw[4];
#pragma unroll
    for (int p = 0; p < 4; p++) {
        int r = nw * 64 + p * 16 + ((lane >> 4) & 1) * 8 + (lane & 7);
        boff[p] = r * ROWB;
        bsw[p]  = (r & 7) << 4;
    }
    const int bkh = ((lane >> 3) & 1) * 16;

    auto load_chunk = [&](int s, int c) {
        uint32_t dA = sbase + s * STAGE;
        uint32_t dB = dA + HALF;
#pragma unroll
        for (int i = tid; i < 16 * CK; i += 256) {
            int row = i / CPR, cc = i % CPR;
            int so = swzo(cc * 16, (row & 7) << 4);
            cp16(dA + row * ROWB + so,
                 Ab + (size_t)row * (KTOT * 2) + c * (CK * 2) + cc * 16);
            cp16(dB + row * ROWB + so,
                 WTb + (size_t)row * (KTOT * 2) + c * (CK * 2) + cc * 16);
        }
        asm volatile("cp.async.commit_group;" ::: "memory");
    };

    auto compute = [&](int s) {
        uint32_t bA = sbase + s * STAGE;
        uint32_t bB = bA + HALF;
#pragma unroll
        for (int kk = 0; kk < CK; kk += 16) {
            uint32_t a[2][4], bb[4][4];
#pragma unroll
            for (int mt = 0; mt < 2; mt++)
                ldsm_x4(a[mt], bA + aoff[mt] + swzo(kk * 2 + akh, asw[mt]));
#pragma unroll
            for (int p = 0; p < 4; p++)
                ldsm_x4(bb[p], bB + boff[p] + swzo(kk * 2 + bkh, bsw[p]));
#pragma unroll
            for (int mt = 0; mt < 2; mt++)
#pragma unroll
                for (int nt = 0; nt < 8; nt++) {
                    int p = nt >> 1, hi = (nt & 1) * 2;
                    mma16816(acc[mt][nt], a[mt], bb[p][hi], bb[p][hi + 1]);
                }
        }
    };

    load_chunk(0, 0);
    if (CHUNKS > 1) load_chunk(1, 1);

#pragma unroll 1
    for (int c = 0; c < CHUNKS; c++) {
        if (CHUNKS > 1 && c < CHUNKS - 1)
            asm volatile("cp.async.wait_group 1;" ::: "memory");
        else
            asm volatile("cp.async.wait_group 0;" ::: "memory");
        __syncthreads();
        compute(c & (STAGES - 1));
        if (CHUNKS > 1 && c + 2 <= CHUNKS - 1) {
            __syncthreads();
            load_chunk(c & 1, c + 2);
        }
    }

    // ---- epilogue ----
    const int g4 = lane >> 2, t4 = lane & 3;
#pragma unroll
    for (int mt = 0; mt < 2; mt++) {
        int row = blockIdx.x * 128 + mw * 32 + mt * 16 + g4;
#pragma unroll
        for (int nt = 0; nt < 8; nt++) {
            int cl = nw * 64 + nt * 8 + 2 * t4;
            float* ac = acc[mt][nt];
            if (EPI == 0) {
                int cg = blockIdx.y * 128 + cl;
                float b0 = bias[cg], b1 = bias[cg + 1];
                float v0 = ac[0] + b0, v1 = ac[1] + b1;
                float v2 = ac[2] + b0, v3 = ac[3] + b1;
                if (blockIdx.y == 0) { v0 *= SCALE_Q; v1 *= SCALE_Q; v2 *= SCALE_Q; v3 *= SCALE_Q; }
                __nv_bfloat16* out = (__nv_bfloat16*)Cv;
                *reinterpret_cast<__nv_bfloat162*>(out + (size_t)row * 384 + cg) =
                    __floats2bfloat162_rn(v0, v1);
                *reinterpret_cast<__nv_bfloat162*>(out + (size_t)(row + 8) * 384 + cg) =
                    __floats2bfloat162_rn(v2, v3);
            } else if (EPI == 2) {
                int cg = blockIdx.y * 128 + cl;
                float b0 = bias[cg], b1 = bias[cg + 1];
                __nv_bfloat16* out = (__nv_bfloat16*)Cv;
                *reinterpret_cast<__nv_bfloat162*>(out + (size_t)row * 512 + cg) =
                    __floats2bfloat162_rn(gelu_f(ac[0] + b0), gelu_f(ac[1] + b1));
                *reinterpret_cast<__nv_bfloat162*>(out + (size_t)(row + 8) * 512 + cg) =
                    __floats2bfloat162_rn(gelu_f(ac[2] + b0), gelu_f(ac[3] + b1));
            } else {
                float b0 = bias[cl], b1 = bias[cl + 1];
                float* out = (float*)Cv;
                if (row < M) {
                    float2 rr = *reinterpret_cast<const float2*>(res + (size_t)row * 128 + cl);
                    *reinterpret_cast<float2*>(out + (size_t)row * 128 + cl) =
                        make_float2(ac[0] + b0 + rr.x, ac[1] + b1 + rr.y);
                }
                if (row + 8 < M) {
                    float2 rr = *reinterpret_cast<const float2*>(res + (size_t)(row + 8) * 128 + cl);
                    *reinterpret_cast<float2*>(out + (size_t)(row + 8) * 128 + cl) =
                        make_float2(ac[2] + b0 + rr.x, ac[3] + b1 + rr.y);
                }
            }
        }
    }
}

// ---------------------------------------------------------------------------
// Fused attention: per (node, slot) gather q/k, score, softmax, v-aggregate.
// 4 nodes per 256-thread block.
// ---------------------------------------------------------------------------
__global__ void __launch_bounds__(256) attn_fused_kernel(
    const int* __restrict__ inc_idx, const int* __restrict__ src,
    const int* __restrict__ dst, const float* __restrict__ eb,
    const __nv_bfloat16* __restrict__ qkv,
    __nv_bfloat16* __restrict__ attn, int N)
{
    int tid = threadIdx.x;
    int base_n = blockIdx.x * 4;
    __shared__ int   e_sm[4][16];
    __shared__ int   s_row[4][16];
    __shared__ int   d_row[4][16];
    __shared__ float s_sm[4][16][8];
    __shared__ float w_sm[4][16][8];

    // Phase A: indices (64 threads)
    if (tid < 64) {
        int which = tid >> 4, k = tid & 15;
        int n = base_n + which;
        int e = 0;
        if (n < N) {
            e = inc_idx[(size_t)n * 16 + k];
            if (e < 0) e = 0;
        }
        e_sm[which][k] = e;
        s_row[which][k] = src[e];
        d_row[which][k] = dst[e];
    }
    __syncthreads();

    // Phase B: scores — 512 cells (which,k,h), 2 per thread
#pragma unroll
    for (int cc = 0; cc < 2; cc++) {
        int c = tid + cc * 256;
        int which = c >> 7, kk = (c >> 3) & 15, h = c & 7;
        int s = s_row[which][kk], d = d_row[which][kk];
        const uint4* qp = reinterpret_cast<const uint4*>(qkv + (size_t)s * 384 + h * 16);
        const uint4* kp = reinterpret_cast<const uint4*>(qkv + (size_t)d * 384 + 128 + h * 16);
        uint4 q0 = qp[0], q1 = qp[1];
        uint4 k0 = kp[0], k1 = kp[1];
        float acc = 0.0f;
#define DOT2(ua, ub) { \
    float2 fa = __bfloat1622float2(*reinterpret_cast<__nv_bfloat162*>(&(ua))); \
    float2 fb = __bfloat1622float2(*reinterpret_cast<__nv_bfloat162*>(&(ub))); \
    acc = fmaf(fa.x, fb.x, acc); acc = fmaf(fa.y, fb.y, acc); }
        DOT2(q0.x, k0.x) DOT2(q0.y, k0.y) DOT2(q0.z, k0.z) DOT2(q0.w, k0.w)
        DOT2(q1.x, k1.x) DOT2(q1.y, k1.y) DOT2(q1.z, k1.z) DOT2(q1.w, k1.w)
#undef DOT2
        s_sm[which][kk][h] = acc + eb[(size_t)e_sm[which][kk] * 8 + h];
    }
    __syncthreads();

    // Phase C: softmax per (node, head) — 32 threads
    if (tid < 32) {
        int which = tid >> 3, h = tid & 7;
        float mx = -1e30f;
#pragma unroll
        for (int k = 0; k < 16; k++) mx = fmaxf(mx, s_sm[which][k][h]);
        float ex[16], se = 0.0f;
#pragma unroll
        for (int k = 0; k < 16; k++) { ex[k] = __expf(s_sm[which][k][h] - mx); se += ex[k]; }
        float inv = 1.0f / se;
#pragma unroll
        for (int k = 0; k < 16; k++) w_sm[which][k][h] = ex[k] * inv;
    }
    __syncthreads();

    // Phase D: weighted v — 64 threads per node, 2 dims each
    int which = tid >> 6, lt = tid & 63, dd = lt * 2, h = dd >> 4;
    int n = base_n + which;
    if (n < N) {
        float a0 = 0.0f, a1 = 0.0f;
#pragma unroll
        for (int k = 0; k < 16; k++) {
            uint32_t u = *reinterpret_cast<const uint32_t*>(
                qkv + (size_t)s_row[which][k] * 384 + 256 + dd);
            float2 f = __bfloat1622float2(*reinterpret_cast<__nv_bfloat162*>(&u));
            float w = w_sm[which][k][h];
            a0 = fmaf(w, f.x, a0);
            a1 = fmaf(w, f.y, a1);
        }
        *reinterpret_cast<__nv_bfloat162*>(attn + (size_t)n * 128 + dd) =
            __floats2bfloat162_rn(a0, a1);
    }
}

// ---------------------------------------------------------------------------
// Host launcher
// ---------------------------------------------------------------------------
extern "C" void kernel_launch(void* const* d_in, const int* in_sizes, int n_in,
                              void* d_out, int out_size)
{
    const float* triplet   = (const float*)d_in[0];
    const int*   src       = (const int*)  d_in[2];
    const int*   dst       = (const int*)  d_in[3];
    const float* edge_bias = (const float*)d_in[4];
    const int*   inc_idx   = (const int*)  d_in[6];
    const float* ln1_g     = (const float*)d_in[8];
    const float* ln1_b     = (const float*)d_in[9];
    const float* qkv_w     = (const float*)d_in[10];
    const float* qkv_b     = (const float*)d_in[11];
    const float* res_in_w  = (const float*)d_in[12];
    const float* res_in_b  = (const float*)d_in[13];
    const float* res_ln_g  = (const float*)d_in[14];
    const float* res_ln_b  = (const float*)d_in[15];
    const float* ffn_in_w  = (const float*)d_in[16];
    const float* ffn_in_b  = (const float*)d_in[17];
    const float* ffn_out_w = (const float*)d_in[18];
    const float* ffn_out_b = (const float*)d_in[19];

    const int N = in_sizes[0] / 128;
    const int E = in_sizes[2];
    const int NT = (N + 127) / 128;
    (void)E;

    __nv_bfloat16 *xln, *attn, *hid, *qkv, *wq, *wr, *w1, *w2;
    float *x2;
    cudaGetSymbolAddress((void**)&xln,  g_xln);
    cudaGetSymbolAddress((void**)&attn, g_attn);
    cudaGetSymbolAddress((void**)&hid,  g_hid);
    cudaGetSymbolAddress((void**)&qkv,  g_qkv);
    cudaGetSymbolAddress((void**)&x2,   g_x2);
    cudaGetSymbolAddress((void**)&wq,   g_wq);
    cudaGetSymbolAddress((void**)&wr,   g_wr);
    cudaGetSymbolAddress((void**)&w1,   g_w1);
    cudaGetSymbolAddress((void**)&w2,   g_w2);

    const int SMEM = 65536;
    cudaFuncSetAttribute(gemm_mma<0, 128, 128>, cudaFuncAttributeMaxDynamicSharedMemorySize, SMEM);
    cudaFuncSetAttribute(gemm_mma<1, 128, 128>, cudaFuncAttributeMaxDynamicSharedMemorySize, SMEM);
    cudaFuncSetAttribute(gemm_mma<2, 128, 128>, cudaFuncAttributeMaxDynamicSharedMemorySize, SMEM);
    cudaFuncSetAttribute(gemm_mma<3, 512, 64>,  cudaFuncAttributeMaxDynamicSharedMemorySize, SMEM);

    dim3 lnb(32, 8);
    int  lng = (N + 7) / 8;

    // 0) weight prep
    prep_weights<<<768, 256>>>(qkv_w, res_in_w, ffn_in_w, ffn_out_w, wq, wr, w1, w2);

    // 1) xln = LN(triplet_h)
    ln_kernel<<<lng, lnb>>>(triplet, ln1_g, ln1_b, xln, N);

    // 2) qkv = xln @ qkv_w + qkv_b
    gemm_mma<0, 128, 128><<<dim3(NT, 3), 256, SMEM>>>(xln, wq, qkv_b, nullptr, qkv, N);

    // 3) fused scores + softmax + aggregation
    attn_fused_kernel<<<(N + 3) / 4, 256>>>(inc_idx, src, dst, edge_bias, qkv, attn, N);

    // 4) x2 = triplet_h + attn @ res_in_w + res_in_b
    gemm_mma<1, 128, 128><<<dim3(NT, 1), 256, SMEM>>>(attn, wr, res_in_b, triplet, x2, N);

    // 5) xln = LN(x2)
    ln_kernel<<<lng, lnb>>>(x2, res_ln_g, res_ln_b, xln, N);

    // 6) hid = gelu(xln @ ffn_in_w + ffn_in_b)
    gemm_mma<2, 128, 128><<<dim3(NT, 4), 256, SMEM>>>(xln, w1, ffn_in_b, nullptr, hid, N);

    // 7) out = x2 + hid @ ffn_out_w + ffn_out_b
    gemm_mma<3, 512, 64><<<dim3(NT, 1), 256, SMEM>>>(hid, w2, ffn_out_b, x2, d_out, N);
}